// round 10
// baseline (speedup 1.0000x reference)
#include <cuda_runtime.h>
#include <cuda_bf16.h>

// Problem constants
#define Bsz   128
#define Tlen  80
#define Edim  100
#define Udim  512

// Launch: 128 CTAs = 4 pairs x 32 col-slices; 512 threads (16 warps).
// CTA (p, j) owns col-slice j and TWO 16-row sets s0=2p, s1=2p+1,
// processed phase-skewed: A(s0) A(s1) B(s0) B(s1) per step.
#define NCTA  128
#define NTHR  512
#define GSZ   32            // CTAs per sync group (one row-set)
#define NSET  8
#define PADK  516
#define RPAD  40            // reduction pad: bank = 8*row+col distinct

// SMEM layout (float offsets)
#define OFF_WA 0                          // 32 cols x PADK (phase-A slice)
#define OFF_WB (32 * PADK)                // 16 cols x PADK (phase-B slice)
#define OFF_H  (48 * PADK)                // 16 rows x PADK (single H tile)
#define OFF_RED (64 * PADK)               // 8 K-slices x 16 x RPAD
#define SMEM_FLOATS (OFF_RED + 8 * 16 * RPAD)
#define SMEM_BYTES  (SMEM_FLOATS * 4)     // 152576 B

typedef unsigned long long u64;

// Device-global scratch
__device__ float g_P0[Tlen * Bsz * Udim];
__device__ float g_h [Bsz * Udim];
__device__ float g_h0[Bsz * Udim];
__device__ float g_r1[Bsz * Udim];
__device__ unsigned g_cA[NSET * 32];    // per-set phase-A counters (128B apart)
__device__ unsigned g_cB[NSET * 32];

// ---------------- helpers ----------------

__device__ __forceinline__ u64 ffma2(u64 a, u64 b, u64 c) {
    u64 d;
    asm("fma.rn.f32x2 %0, %1, %2, %3;" : "=l"(d) : "l"(a), "l"(b), "l"(c));
    return d;
}

__device__ __forceinline__ float fsum(u64 v) {
    float lo, hi;
    asm("mov.b64 {%0, %1}, %2;" : "=f"(lo), "=f"(hi) : "l"(v));
    return lo + hi;
}

__device__ __forceinline__ float tanh_fast(float x) {
    float e = __expf(2.0f * x);
    return 1.0f - __fdividef(2.0f, e + 1.0f);
}

// One-thread poll + block sync (R4-proven mechanics).
__device__ __forceinline__ void wait_ctr(const unsigned* c, unsigned target) {
    if (threadIdx.x == 0) {
        unsigned v;
        do {
            asm volatile("ld.acquire.gpu.global.u32 %0, [%1];"
                         : "=r"(v) : "l"(c) : "memory");
        } while (v < target);
    }
    __syncthreads();
}

__device__ __forceinline__ void arrive_ctr(unsigned* c) {
    // caller guarantees a preceding __syncthreads after the data stores
    if (threadIdx.x == 0)
        asm volatile("red.release.gpu.global.add.u32 [%0], %1;"
                     :: "l"(c), "r"(1u) : "memory");
}

// ---------------- kernel 1: P0 = emb[tokens] @ k0 + b0 ----------------

#define PC_PAIRS 16
#define PTHR 128

__global__ void __launch_bounds__(PTHR) pre_kernel(
    const int* __restrict__ tokens, const float* __restrict__ emb,
    const float* __restrict__ k0, const float* __restrict__ b0)
{
    __shared__ int    tok[PC_PAIRS];
    __shared__ float2 xs2[PC_PAIRS][Edim];

    const int tid = threadIdx.x;

    if (blockIdx.x == 0 && tid < NSET) {
        g_cA[tid * 32] = 0u;
        g_cB[tid * 32] = 0u;
    }

    if (blockIdx.x < 64) {
        int base = blockIdx.x * 1024 + tid * 8;
        float4 z = make_float4(0.f, 0.f, 0.f, 0.f);
        *(float4*)(g_h + base)     = z;
        *(float4*)(g_h + base + 4) = z;
    }

    const int pbase = blockIdx.x * PC_PAIRS;
    if (tid < PC_PAIRS) tok[tid] = tokens[pbase + tid];
    __syncthreads();

    for (int e = tid; e < PC_PAIRS * Edim; e += PTHR) {
        int p = e / Edim, k = e - p * Edim;
        float v = emb[tok[p] * Edim + k];
        xs2[p][k] = make_float2(v, v);
    }
    __syncthreads();

    const int u = tid * 4;
    u64 acc[PC_PAIRS][2];
#pragma unroll
    for (int p = 0; p < PC_PAIRS; p++) { acc[p][0] = 0ull; acc[p][1] = 0ull; }

    for (int k = 0; k < Edim; k++) {
        ulonglong2 wv = *(const ulonglong2*)(k0 + k * Udim + u);
#pragma unroll
        for (int p = 0; p < PC_PAIRS; p++) {
            u64 x2 = *(const u64*)&xs2[p][k];
            acc[p][0] = ffma2(x2, wv.x, acc[p][0]);
            acc[p][1] = ffma2(x2, wv.y, acc[p][1]);
        }
    }

    float4 bv = *(const float4*)(b0 + u);
#pragma unroll
    for (int p = 0; p < PC_PAIRS; p++) {
        int pi = pbase + p;
        int b = pi / Tlen;
        int t = pi - b * Tlen;
        float2 lo, hi;
        asm("mov.b64 {%0, %1}, %2;" : "=f"(lo.x), "=f"(lo.y) : "l"(acc[p][0]));
        asm("mov.b64 {%0, %1}, %2;" : "=f"(hi.x), "=f"(hi.y) : "l"(acc[p][1]));
        float4 o = make_float4(lo.x + bv.x, lo.y + bv.y, hi.x + bv.z, hi.y + bv.w);
        *(float4*)(g_P0 + ((size_t)(t * Bsz) + b) * Udim + u) = o;
    }
}

// ---------------- kernel 2: persistent scan, phase-skewed sets ----------------
// Warps: q = w>>1 (K-slice [64q,64q+64)), hh = w&1 (rows [8hh, 8hh+8)).
// Warp FMA tile A: 8 rows x 32 cols; thread 2r x 4c (rg=lane&3 rows rg+4i,
// cg=lane>>2 cols cg+8jj). B: 8 rows x 16 cols; thread 2r x 2c.
// Per-warp strip load: own 8 rows x 64 cols window; __syncwarp only.

__global__ void __launch_bounds__(NTHR, 1) rnn_kernel(
    const float* __restrict__ rk0, const float* __restrict__ rk1,
    const float* __restrict__ k1,  const float* __restrict__ b1,
    const float* __restrict__ wd,  const float* __restrict__ bd,
    float* __restrict__ out)
{
    extern __shared__ float sm[];
    const int tid  = threadIdx.x;
    const int p    = blockIdx.x >> 5;
    const int j    = blockIdx.x & 31;
    const int w    = tid >> 5;
    const int lane = tid & 31;
    const int q    = w >> 1;
    const int hh   = w & 1;
    const bool isA0 = (j < 16);
    const int s0 = 2 * p, s1 = 2 * p + 1;

    // --- weights into SMEM (once), transposed [col][K] ---
    const float* wsrcA = isA0 ? rk0 : rk1;
    const int cbaseA = (j & 15) * 32;
    for (int e = tid; e < 32 * Udim; e += NTHR) {
        int k = e >> 5, cc = e & 31;
        sm[OFF_WA + cc * PADK + k] = wsrcA[k * Udim + cbaseA + cc];
    }
    const int cbaseB = j * 16;
    for (int e = tid; e < 16 * Udim; e += NTHR) {
        int k = e >> 4, cc = e & 15;
        sm[OFF_WB + cc * PADK + k] = k1[k * Udim + cbaseB + cc];
    }

    // FMA lane geometry
    const int rg = lane & 3;         // rows 8hh + rg + 4i (i<2)
    const int cg = lane >> 2;        // cols cg + 8jj

    // finalize geometry
    const int frA = tid >> 5;        // 0..15 (row within set)   A: 1 out/thread
    const int fcA = tid & 31;        // col 0..31
    const int frB = tid >> 4;        // 0..15 for tid<256        B: 1 out/thread
    const int fcB = tid & 15;

    float b1v = 0.f;
    if (!isA0) b1v = b1[cbaseA + fcA];
    __syncthreads();

    // per-warp pointers
    const float* Hp  = sm + OFF_H  + hh * 8 * PADK + q * 64;  // + (rg+4i)*PADK + k
    const float* WpA = sm + OFF_WA + q * 64;
    const float* WpB = sm + OFF_WB + q * 64;
    float* redq = sm + OFF_RED + q * (16 * RPAD);

    // strip-load lane geometry: rows rs = 8hh + (lane>>2), f4 idx (lane&3)+4i
    const int rs = 8 * hh + (lane >> 2);
    const int f0 = lane & 3;
    float* HTw = sm + OFF_H + rs * PADK + q * 64;

    unsigned* cA[2] = { g_cA + s0 * 32, g_cA + s1 * 32 };
    unsigned* cB[2] = { g_cB + s0 * 32, g_cB + s1 * 32 };
    const int rbase[2] = { 16 * s0, 16 * s1 };

    for (int t = 0; t < Tlen; t++) {
        // ================= Phase A: h @ [rk0 | rk1], sets e=0,1 =========
#pragma unroll 1
        for (int e = 0; e < 2; e++) {
            wait_ctr(cB[e], (unsigned)(GSZ * t));   // h(t) of set e ready

            float pv = 0.f;
            if (isA0)
                pv = __ldcg(g_P0 + ((size_t)t * Bsz + rbase[e] + frA) * Udim
                            + cbaseA + fcA);

            // per-warp strip: 8 rows x 64 cols of h(set e)
            {
                const float* src = g_h + (size_t)(rbase[e] + rs) * Udim + 64 * q;
                float4 tmp[4];
#pragma unroll
                for (int i = 0; i < 4; i++)
                    tmp[i] = __ldcg((const float4*)src + f0 + 4 * i);
#pragma unroll
                for (int i = 0; i < 4; i++)
                    *(float4*)(HTw + (f0 + 4 * i) * 4) = tmp[i];
                __syncwarp();
            }

            u64 acc[2][4];
#pragma unroll
            for (int i = 0; i < 2; i++)
#pragma unroll
                for (int jj = 0; jj < 4; jj++) acc[i][jj] = 0ull;

#pragma unroll 4
            for (int kc = 0; kc < 16; kc++) {
                const int k = kc * 4;
                ulonglong2 Wv[4];
#pragma unroll
                for (int jj = 0; jj < 4; jj++)
                    Wv[jj] = *(const ulonglong2*)(WpA + (cg + 8 * jj) * PADK + k);
#pragma unroll
                for (int i = 0; i < 2; i++) {
                    ulonglong2 Hv = *(const ulonglong2*)(Hp + (rg + 4 * i) * PADK + k);
#pragma unroll
                    for (int jj = 0; jj < 4; jj++) {
                        acc[i][jj] = ffma2(Hv.x, Wv[jj].x, acc[i][jj]);
                        acc[i][jj] = ffma2(Hv.y, Wv[jj].y, acc[i][jj]);
                    }
                }
            }

            // partials: bank = 8*rg + cg (+consts) -> conflict-free
#pragma unroll
            for (int i = 0; i < 2; i++)
#pragma unroll
                for (int jj = 0; jj < 4; jj++)
                    redq[(8 * hh + rg + 4 * i) * RPAD + cg + 8 * jj] =
                        fsum(acc[i][jj]);
            __syncthreads();

            // finalize: 1 output/thread over 8 K-slice partials
            {
                float s = 0.f;
#pragma unroll
                for (int qq = 0; qq < 8; qq++)
                    s += sm[OFF_RED + qq * (16 * RPAD) + frA * RPAD + fcA];
                int grow = (rbase[e] + frA) * Udim + cbaseA + fcA;
                if (isA0) g_h0[grow] = tanh_fast(s + pv);
                else      g_r1[grow] = s + b1v;
            }
            __syncthreads();
            arrive_ctr(cA[e]);
        }

        // ================= Phase B: h0 @ k1, sets e=0,1 =================
#pragma unroll 1
        for (int e = 0; e < 2; e++) {
            wait_ctr(cA[e], (unsigned)(GSZ * (t + 1)));

            float r1v = 0.f;
            if (tid < 256)
                r1v = __ldcg(g_r1 + (size_t)(rbase[e] + frB) * Udim + cbaseB + fcB);

            {
                const float* src = g_h0 + (size_t)(rbase[e] + rs) * Udim + 64 * q;
                float4 tmp[4];
#pragma unroll
                for (int i = 0; i < 4; i++)
                    tmp[i] = __ldcg((const float4*)src + f0 + 4 * i);
#pragma unroll
                for (int i = 0; i < 4; i++)
                    *(float4*)(HTw + (f0 + 4 * i) * 4) = tmp[i];
                __syncwarp();
            }

            u64 acc2[2][2];
#pragma unroll
            for (int i = 0; i < 2; i++) { acc2[i][0] = 0ull; acc2[i][1] = 0ull; }

#pragma unroll 4
            for (int kc = 0; kc < 16; kc++) {
                const int k = kc * 4;
                ulonglong2 Wv[2];
#pragma unroll
                for (int jj = 0; jj < 2; jj++)
                    Wv[jj] = *(const ulonglong2*)(WpB + (cg + 8 * jj) * PADK + k);
#pragma unroll
                for (int i = 0; i < 2; i++) {
                    ulonglong2 Hv = *(const ulonglong2*)(Hp + (rg + 4 * i) * PADK + k);
#pragma unroll
                    for (int jj = 0; jj < 2; jj++) {
                        acc2[i][jj] = ffma2(Hv.x, Wv[jj].x, acc2[i][jj]);
                        acc2[i][jj] = ffma2(Hv.y, Wv[jj].y, acc2[i][jj]);
                    }
                }
            }

#pragma unroll
            for (int i = 0; i < 2; i++)
#pragma unroll
                for (int jj = 0; jj < 2; jj++)
                    redq[(8 * hh + rg + 4 * i) * RPAD + cg + 8 * jj] =
                        fsum(acc2[i][jj]);
            __syncthreads();

            if (tid < 256) {
                float s = 0.f;
#pragma unroll
                for (int qq = 0; qq < 8; qq++)
                    s += sm[OFF_RED + qq * (16 * RPAD) + frB * RPAD + fcB];
                g_h[(rbase[e] + frB) * Udim + cbaseB + fcB] = tanh_fast(s + r1v);
            }
            __syncthreads();
            arrive_ctr(cB[e]);
        }
    }

    // ---- output head: CTA j==0 of each pair handles its 32 rows ----
    if (j == 0) {
        wait_ctr(cB[0], (unsigned)(GSZ * Tlen));
        wait_ctr(cB[1], (unsigned)(GSZ * Tlen));

        int row = 32 * p + (tid >> 4);        // 32 rows, 16 threads each
        int pp  = tid & 15;
        const float4* hv = (const float4*)(g_h + row * Udim + pp * 32);
        const float4* wv = (const float4*)(wd + pp * 32);
        float s = 0.f;
#pragma unroll
        for (int qq = 0; qq < 8; qq++) {
            float4 a = __ldcg(hv + qq);
            float4 b = wv[qq];
            s += a.x * b.x + a.y * b.y + a.z * b.z + a.w * b.w;
        }
        s += __shfl_xor_sync(0xffffffffu, s, 1);
        s += __shfl_xor_sync(0xffffffffu, s, 2);
        s += __shfl_xor_sync(0xffffffffu, s, 4);
        s += __shfl_xor_sync(0xffffffffu, s, 8);
        if (pp == 0) out[row] = 1.0f / (1.0f + __expf(-(s + bd[0])));
    }
}

// ---------------- launch ----------------

extern "C" void kernel_launch(void* const* d_in, const int* in_sizes, int n_in,
                              void* d_out, int out_size) {
    const int*   tokens = (const int*)  d_in[0];
    const float* emb    = (const float*)d_in[1];
    const float* k0     = (const float*)d_in[2];
    const float* rk0    = (const float*)d_in[3];
    const float* b0     = (const float*)d_in[4];
    const float* k1     = (const float*)d_in[5];
    const float* rk1    = (const float*)d_in[6];
    const float* b1     = (const float*)d_in[7];
    const float* wd     = (const float*)d_in[8];
    const float* bd     = (const float*)d_in[9];
    float* out = (float*)d_out;

    (void)in_sizes; (void)n_in; (void)out_size;

    cudaFuncSetAttribute(rnn_kernel, cudaFuncAttributeMaxDynamicSharedMemorySize, SMEM_BYTES);

    pre_kernel<<<(Bsz * Tlen) / PC_PAIRS, PTHR>>>(tokens, emb, k0, b0);
    rnn_kernel<<<NCTA, NTHR, SMEM_BYTES>>>(rk0, rk1, k1, b1, wd, bd, out);
}

// round 12
// speedup vs baseline: 1.3777x; 1.3777x over previous
#include <cuda_runtime.h>
#include <cuda_bf16.h>

// Problem constants
#define Bsz   128
#define Tlen  80
#define Edim  100
#define Udim  512

// Launch shape: 4 independent row-groups x 32 col-slice CTAs, 8 warps/CTA
#define NCTA  128
#define NTHR  256
#define NWARP 8
#define GSZ   32
#define NGRP  4
#define RPC   32
#define PADK  516

#define APAD  40            // phase-A reduction pad
#define BPAD  20            // phase-B reduction pad

// SMEM layout (float offsets)
#define OFF_WA 0                          // 32 cols x PADK
#define OFF_WB (32 * PADK)                // 16 cols x PADK
#define OFF_H  (OFF_WB + 16 * PADK)       // 32 rows x PADK
#define OFF_RED (OFF_H + RPC * PADK)      // 8 warps x 32 x APAD
#define SMEM_FLOATS (OFF_RED + NWARP * 32 * APAD)
#define SMEM_BYTES  (SMEM_FLOATS * 4)     // 206080 B

typedef unsigned long long u64;

// Device-global scratch
__device__ float g_P0[Tlen * Bsz * Udim];
__device__ float g_h [Bsz * Udim];
__device__ float g_h0[Bsz * Udim];
__device__ float g_r1[Bsz * Udim];
// per-group counters, 128B-padded. Arrivals are PER-WARP (x8).
__device__ unsigned g_cA0[NGRP * 32];   // cell-0 A done (h0 ready)   128/step
__device__ unsigned g_cA1[NGRP * 32];   // cell-1 A done (r1 ready)   128/step
__device__ unsigned g_cB [NGRP * 32];   // B done (h ready)           256/step

// ---------------- helpers ----------------

__device__ __forceinline__ u64 ffma2(u64 a, u64 b, u64 c) {
    u64 d;
    asm("fma.rn.f32x2 %0, %1, %2, %3;" : "=l"(d) : "l"(a), "l"(b), "l"(c));
    return d;
}

__device__ __forceinline__ float fsum(u64 v) {
    float lo, hi;
    asm("mov.b64 {%0, %1}, %2;" : "=f"(lo), "=f"(hi) : "l"(v));
    return lo + hi;
}

__device__ __forceinline__ float tanh_fast(float x) {
    float e = __expf(2.0f * x);
    return 1.0f - __fdividef(2.0f, e + 1.0f);
}

// Wait: ONE thread polls, then block sync (R4-proven safe).
__device__ __forceinline__ void wait_ctr(const unsigned* c, unsigned target) {
    if (threadIdx.x == 0) {
        unsigned v;
        do {
            asm volatile("ld.acquire.gpu.global.u32 %0, [%1];"
                         : "=r"(v) : "l"(c) : "memory");
        } while (v < target);
    }
    __syncthreads();
}

// Per-warp arrive: syncwarp orders the warp's prior stores, lane 0 releases.
__device__ __forceinline__ void warp_arrive(unsigned* c) {
    __syncwarp();
    if ((threadIdx.x & 31) == 0)
        asm volatile("red.release.gpu.global.add.u32 [%0], %1;"
                     :: "l"(c), "r"(1u) : "memory");
}

// Load 32 rows x 512 cols into padded SMEM tile (L2-only loads). 256 threads.
__device__ __forceinline__ void load_ht(float* HT, const float* src) {
    const float4* s = (const float4*)src;
#pragma unroll
    for (int i = 0; i < 16; i++) {
        int e = threadIdx.x + i * NTHR;      // 0..4095
        int r = e >> 7, kq = e & 127;
        float4 v = __ldcg(s + e);
        *(float4*)(HT + r * PADK + (kq << 2)) = v;
    }
}

// ---------------- kernel 1: P0 = emb[tokens] @ k0 + b0 ----------------

#define PC_PAIRS 16
#define PTHR 128

__global__ void __launch_bounds__(PTHR) pre_kernel(
    const int* __restrict__ tokens, const float* __restrict__ emb,
    const float* __restrict__ k0, const float* __restrict__ b0)
{
    __shared__ int    tok[PC_PAIRS];
    __shared__ float2 xs2[PC_PAIRS][Edim];

    const int tid = threadIdx.x;

    if (blockIdx.x == 0 && tid < NGRP) {
        g_cA0[tid * 32] = 0u;
        g_cA1[tid * 32] = 0u;
        g_cB [tid * 32] = 0u;
    }

    if (blockIdx.x < 64) {
        int base = blockIdx.x * 1024 + tid * 8;
        float4 z = make_float4(0.f, 0.f, 0.f, 0.f);
        *(float4*)(g_h + base)     = z;
        *(float4*)(g_h + base + 4) = z;
    }

    const int pbase = blockIdx.x * PC_PAIRS;
    if (tid < PC_PAIRS) tok[tid] = tokens[pbase + tid];
    __syncthreads();

    for (int e = tid; e < PC_PAIRS * Edim; e += PTHR) {
        int p = e / Edim, k = e - p * Edim;
        float v = emb[tok[p] * Edim + k];
        xs2[p][k] = make_float2(v, v);
    }
    __syncthreads();

    const int u = tid * 4;
    u64 acc[PC_PAIRS][2];
#pragma unroll
    for (int p = 0; p < PC_PAIRS; p++) { acc[p][0] = 0ull; acc[p][1] = 0ull; }

    for (int k = 0; k < Edim; k++) {
        ulonglong2 wv = *(const ulonglong2*)(k0 + k * Udim + u);
#pragma unroll
        for (int p = 0; p < PC_PAIRS; p++) {
            u64 x2 = *(const u64*)&xs2[p][k];
            acc[p][0] = ffma2(x2, wv.x, acc[p][0]);
            acc[p][1] = ffma2(x2, wv.y, acc[p][1]);
        }
    }

    float4 bv = *(const float4*)(b0 + u);
#pragma unroll
    for (int p = 0; p < PC_PAIRS; p++) {
        int pi = pbase + p;
        int b = pi / Tlen;
        int t = pi - b * Tlen;
        float2 lo, hi;
        asm("mov.b64 {%0, %1}, %2;" : "=f"(lo.x), "=f"(lo.y) : "l"(acc[p][0]));
        asm("mov.b64 {%0, %1}, %2;" : "=f"(hi.x), "=f"(hi.y) : "l"(acc[p][1]));
        float4 o = make_float4(lo.x + bv.x, lo.y + bv.y, hi.x + bv.z, hi.y + bv.w);
        *(float4*)(g_P0 + ((size_t)(t * Bsz) + b) * Udim + u) = o;
    }
}

// ---------------- kernel 2: persistent scan ----------------
// CTA (g, j): g = row group (32 rows), j = col slice. 8 warps; warp w owns
// K-slice [64w, 64w+64). Sync (per-warp arrivals, x8 targets):
//   A-FMA(t) waits  cB  >= 256*t      (full h(t))
//   B-FMA(t) waits  cA0 >= 128*(t+1)  (h0(t): cell-0 CTAs only)
//   B-finalize(t) waits cA1 >= 128*(t+1) (r1(t)), overlapped with partial sync

__global__ void __launch_bounds__(NTHR, 1) rnn_kernel(
    const float* __restrict__ rk0, const float* __restrict__ rk1,
    const float* __restrict__ k1,  const float* __restrict__ b1,
    const float* __restrict__ wd,  const float* __restrict__ bd,
    float* __restrict__ out)
{
    extern __shared__ float sm[];
    const int tid  = threadIdx.x;
    const int g    = blockIdx.x >> 5;
    const int j    = blockIdx.x & 31;
    const int r0   = g * RPC;
    const int w    = tid >> 5;
    const int lane = tid & 31;
    const bool isA0 = (j < 16);

    unsigned* cA0 = g_cA0 + g * 32;
    unsigned* cA1 = g_cA1 + g * 32;
    unsigned* cB  = g_cB  + g * 32;

    // --- load weight slices into SMEM (once), transposed [col][K] ---
    const float* wsrcA = isA0 ? rk0 : rk1;
    const int cbaseA = (j & 15) * 32;
    for (int e = tid; e < 32 * Udim; e += NTHR) {
        int k = e >> 5, cc = e & 31;
        sm[OFF_WA + cc * PADK + k] = wsrcA[k * Udim + cbaseA + cc];
    }
    const int cbaseB = j * 16;
    for (int e = tid; e < 16 * Udim; e += NTHR) {
        int k = e >> 4, cc = e & 15;
        sm[OFF_WB + cc * PADK + k] = k1[k * Udim + cbaseB + cc];
    }

    // warp FMA geometry
    const int rg  = lane & 3;
    const int cg  = lane >> 2;
    const int rgB = lane & 7;
    const int cgB = lane >> 3;

    // finalize geometry (256 threads)
    const int frow = tid >> 3;
    const int fcA  = (tid & 7) * 4;
    const int fcB  = (tid & 7) * 2;

    float4 b1v = make_float4(0.f, 0.f, 0.f, 0.f);
    if (!isA0) b1v = *(const float4*)(b1 + cbaseA + fcA);
    __syncthreads();

    const float* HpA = sm + OFF_H  + w * 64;
    const float* WpA = sm + OFF_WA + w * 64;
    const float* WpB = sm + OFF_WB + w * 64;
    float* redw  = sm + OFF_RED + w * 32 * APAD;
    float* redwB = sm + OFF_RED + w * 32 * BPAD;

    for (int t = 0; t < Tlen; t++) {
        // ================= Phase A: h @ [rk0 | rk1] =================
        float4 pv = make_float4(0.f, 0.f, 0.f, 0.f);
        if (isA0)  // static data: prefetch before the wait
            pv = __ldcg((const float4*)(g_P0 + ((size_t)t * Bsz + r0 + frow) * Udim
                                        + cbaseA + fcA));

        wait_ctr(cB, 256u * (unsigned)t);       // full h(t) ready

        load_ht(sm + OFF_H, g_h + r0 * Udim);
        __syncthreads();

        u64 acc[8][4];
#pragma unroll
        for (int i = 0; i < 8; i++)
#pragma unroll
            for (int jj = 0; jj < 4; jj++) acc[i][jj] = 0ull;

#pragma unroll 2
        for (int kc = 0; kc < 16; kc++) {
            const int k = kc * 4;
            ulonglong2 Wv[4];
#pragma unroll
            for (int jj = 0; jj < 4; jj++)
                Wv[jj] = *(const ulonglong2*)(WpA + (cg + 8 * jj) * PADK + k);
#pragma unroll
            for (int i = 0; i < 8; i++) {
                ulonglong2 Hv = *(const ulonglong2*)(HpA + (rg + 4 * i) * PADK + k);
#pragma unroll
                for (int jj = 0; jj < 4; jj++) {
                    acc[i][jj] = ffma2(Hv.x, Wv[jj].x, acc[i][jj]);
                    acc[i][jj] = ffma2(Hv.y, Wv[jj].y, acc[i][jj]);
                }
            }
        }

        // store partials (bank = 8*rg + cg + const; conflict-free)
#pragma unroll
        for (int i = 0; i < 8; i++)
#pragma unroll
            for (int jj = 0; jj < 4; jj++)
                redw[(rg + 4 * i) * APAD + cg + 8 * jj] = fsum(acc[i][jj]);
        __syncthreads();

        // finalize: 4 outputs/thread, then PER-WARP arrive
        {
            float4 s = make_float4(0.f, 0.f, 0.f, 0.f);
#pragma unroll
            for (int p = 0; p < NWARP; p++) {
                float4 v = *(const float4*)(sm + OFF_RED + p * 32 * APAD
                                            + frow * APAD + fcA);
                s.x += v.x; s.y += v.y; s.z += v.z; s.w += v.w;
            }
            int grow = (r0 + frow) * Udim + cbaseA + fcA;
            if (isA0) {
                float4 o;
                o.x = tanh_fast(s.x + pv.x);
                o.y = tanh_fast(s.y + pv.y);
                o.z = tanh_fast(s.z + pv.z);
                o.w = tanh_fast(s.w + pv.w);
                *(float4*)(g_h0 + grow) = o;
            } else {
                float4 o = make_float4(s.x + b1v.x, s.y + b1v.y,
                                       s.z + b1v.z, s.w + b1v.w);
                *(float4*)(g_r1 + grow) = o;
            }
        }
        warp_arrive(isA0 ? cA0 : cA1);

        // ================= Phase B: h0 @ k1 =================
        wait_ctr(cA0, 128u * (unsigned)(t + 1));   // h0(t) ready (cell-0 only)

        load_ht(sm + OFF_H, g_h0 + r0 * Udim);
        __syncthreads();

        u64 acc2[4][4];
#pragma unroll
        for (int i = 0; i < 4; i++)
#pragma unroll
            for (int jj = 0; jj < 4; jj++) acc2[i][jj] = 0ull;

#pragma unroll 2
        for (int kc = 0; kc < 16; kc++) {
            const int k = kc * 4;
            ulonglong2 Wv[4];
#pragma unroll
            for (int jj = 0; jj < 4; jj++)
                Wv[jj] = *(const ulonglong2*)(WpB + (cgB + 4 * jj) * PADK + k);
#pragma unroll
            for (int i = 0; i < 4; i++) {
                ulonglong2 Hv = *(const ulonglong2*)(HpA + (rgB + 8 * i) * PADK + k);
#pragma unroll
                for (int jj = 0; jj < 4; jj++) {
                    acc2[i][jj] = ffma2(Hv.x, Wv[jj].x, acc2[i][jj]);
                    acc2[i][jj] = ffma2(Hv.y, Wv[jj].y, acc2[i][jj]);
                }
            }
        }

        // store partials: cols cgB + 4*jj (FIXED from R11's 8*jj);
        // bank = 20*rgB + cgB + 4*jj -> all 32 distinct per (i,jj)
#pragma unroll
        for (int i = 0; i < 4; i++)
#pragma unroll
            for (int jj = 0; jj < 4; jj++)
                redwB[(rgB + 8 * i) * BPAD + cgB + 4 * jj] = fsum(acc2[i][jj]);

        // r1 gate + prefetch, overlapped with the partial-store sync
        wait_ctr(cA1, 128u * (unsigned)(t + 1));   // __syncthreads orders partials too
        float2 r1v = __ldcg((const float2*)(g_r1 + (size_t)(r0 + frow) * Udim
                                            + cbaseB + fcB));

        // finalize: 2 outputs/thread, then PER-WARP arrive
        {
            float2 s = make_float2(0.f, 0.f);
#pragma unroll
            for (int p = 0; p < NWARP; p++) {
                float2 v = *(const float2*)(sm + OFF_RED + p * 32 * BPAD
                                            + frow * BPAD + fcB);
                s.x += v.x; s.y += v.y;
            }
            int grow = (r0 + frow) * Udim + cbaseB + fcB;
            float2 o;
            o.x = tanh_fast(s.x + r1v.x);
            o.y = tanh_fast(s.y + r1v.y);
            *(float2*)(g_h + grow) = o;
        }
        warp_arrive(cB);
    }

    // ---- output head: sigmoid(h @ wd + bd), CTA j==0 of each group ----
    if (j == 0) {
        wait_ctr(cB, 256u * (unsigned)Tlen);
        int row = r0 + (tid >> 3);          // 32 rows, 8 threads each
        int p   = tid & 7;
        const float4* hv = (const float4*)(g_h + row * Udim + p * 64);
        const float4* wv = (const float4*)(wd + p * 64);
        float s = 0.f;
#pragma unroll
        for (int q = 0; q < 16; q++) {
            float4 a = __ldcg(hv + q);
            float4 b = wv[q];
            s += a.x * b.x + a.y * b.y + a.z * b.z + a.w * b.w;
        }
        s += __shfl_xor_sync(0xffffffffu, s, 1);
        s += __shfl_xor_sync(0xffffffffu, s, 2);
        s += __shfl_xor_sync(0xffffffffu, s, 4);
        if (p == 0) out[row] = 1.0f / (1.0f + __expf(-(s + bd[0])));
    }
}

// ---------------- launch ----------------

extern "C" void kernel_launch(void* const* d_in, const int* in_sizes, int n_in,
                              void* d_out, int out_size) {
    const int*   tokens = (const int*)  d_in[0];
    const float* emb    = (const float*)d_in[1];
    const float* k0     = (const float*)d_in[2];
    const float* rk0    = (const float*)d_in[3];
    const float* b0     = (const float*)d_in[4];
    const float* k1     = (const float*)d_in[5];
    const float* rk1    = (const float*)d_in[6];
    const float* b1     = (const float*)d_in[7];
    const float* wd     = (const float*)d_in[8];
    const float* bd     = (const float*)d_in[9];
    float* out = (float*)d_out;

    (void)in_sizes; (void)n_in; (void)out_size;

    cudaFuncSetAttribute(rnn_kernel, cudaFuncAttributeMaxDynamicSharedMemorySize, SMEM_BYTES);

    pre_kernel<<<(Bsz * Tlen) / PC_PAIRS, PTHR>>>(tokens, emb, k0, b0);
    rnn_kernel<<<NCTA, NTHR, SMEM_BYTES>>>(rk0, rk1, k1, b1, wd, bd, out);
}

// round 13
// speedup vs baseline: 1.4136x; 1.0260x over previous
#include <cuda_runtime.h>
#include <cuda_bf16.h>

// Problem constants
#define Bsz   128
#define Tlen  80
#define Edim  100
#define Udim  512

// Launch shape: 8 row-groups (16 rows) x 16 col-slice CTAs, 8 warps/CTA.
// Warp (q, hh): q = K-slice [128q, 128q+128), hh = row half [8hh, 8hh+8).
#define NCTA  128
#define NTHR  256
#define GSZ   16
#define NGRP  8
#define RPC   16
#define PADK  516

#define APAD  72            // A reduction pad (bank 8*rg+cg; f4 reads 4-wf)
#define BPAD  40            // B reduction pad

// SMEM layout (float offsets). RED overlaps H (H dead after FMA; extra sync).
#define OFF_WA 0                          // 64 cols x PADK = 132096 B
#define OFF_WB (64 * PADK)                // 32 cols x PADK =  66048 B
#define OFF_H  (96 * PADK)                // 16 rows x PADK =  33024 B
#define OFF_RED OFF_H                     // 4 bufs x 16 x APAD = 18432 B (fits)
#define SMEM_FLOATS (OFF_H + RPC * PADK)
#define SMEM_BYTES  (SMEM_FLOATS * 4)     // 231168 B <= 232448

typedef unsigned long long u64;

// Device-global scratch
__device__ float g_P0[Tlen * Bsz * Udim];
__device__ float g_h [Bsz * Udim];
__device__ float g_h0[Bsz * Udim];
__device__ float g_r1[Bsz * Udim];
__device__ unsigned g_ctr[NGRP * 32];      // one counter per group, 128B apart

// ---------------- helpers ----------------

__device__ __forceinline__ u64 ffma2(u64 a, u64 b, u64 c) {
    u64 d;
    asm("fma.rn.f32x2 %0, %1, %2, %3;" : "=l"(d) : "l"(a), "l"(b), "l"(c));
    return d;
}

__device__ __forceinline__ float fsum(u64 v) {
    float lo, hi;
    asm("mov.b64 {%0, %1}, %2;" : "=f"(lo), "=f"(hi) : "l"(v));
    return lo + hi;
}

__device__ __forceinline__ float tanh_fast(float x) {
    float e = __expf(2.0f * x);
    return 1.0f - __fdividef(2.0f, e + 1.0f);
}

// Group barrier (R4-proven): monotonic counter, release-red arrive +
// acquire-load poll by ONE thread per CTA.
__device__ __forceinline__ void gbar(unsigned* ctr, unsigned target) {
    __syncthreads();
    if (threadIdx.x == 0) {
        asm volatile("red.release.gpu.global.add.u32 [%0], %1;"
                     :: "l"(ctr), "r"(1u) : "memory");
        unsigned v;
        do {
            asm volatile("ld.acquire.gpu.global.u32 %0, [%1];"
                         : "=r"(v) : "l"(ctr) : "memory");
        } while (v < target);
    }
    __syncthreads();
}

// Load 16 rows x 512 cols into padded SMEM tile (L2-only loads). 256 threads.
__device__ __forceinline__ void load_ht(float* HT, const float* src) {
    const float4* s = (const float4*)src;
#pragma unroll
    for (int i = 0; i < 8; i++) {
        int e = threadIdx.x + i * NTHR;      // 0..2047
        int r = e >> 7, kq = e & 127;
        float4 v = __ldcg(s + e);
        *(float4*)(HT + r * PADK + (kq << 2)) = v;
    }
}

// ---------------- kernel 1: P0 = emb[tokens] @ k0 + b0 ----------------

#define PC_PAIRS 16
#define PTHR 128

__global__ void __launch_bounds__(PTHR) pre_kernel(
    const int* __restrict__ tokens, const float* __restrict__ emb,
    const float* __restrict__ k0, const float* __restrict__ b0)
{
    __shared__ int    tok[PC_PAIRS];
    __shared__ float2 xs2[PC_PAIRS][Edim];

    const int tid = threadIdx.x;

    if (blockIdx.x == 0 && tid < NGRP) g_ctr[tid * 32] = 0u;

    if (blockIdx.x < 64) {
        int base = blockIdx.x * 1024 + tid * 8;
        float4 z = make_float4(0.f, 0.f, 0.f, 0.f);
        *(float4*)(g_h + base)     = z;
        *(float4*)(g_h + base + 4) = z;
    }

    const int pbase = blockIdx.x * PC_PAIRS;
    if (tid < PC_PAIRS) tok[tid] = tokens[pbase + tid];
    __syncthreads();

    for (int e = tid; e < PC_PAIRS * Edim; e += PTHR) {
        int p = e / Edim, k = e - p * Edim;
        float v = emb[tok[p] * Edim + k];
        xs2[p][k] = make_float2(v, v);
    }
    __syncthreads();

    const int u = tid * 4;
    u64 acc[PC_PAIRS][2];
#pragma unroll
    for (int p = 0; p < PC_PAIRS; p++) { acc[p][0] = 0ull; acc[p][1] = 0ull; }

    for (int k = 0; k < Edim; k++) {
        ulonglong2 wv = *(const ulonglong2*)(k0 + k * Udim + u);
#pragma unroll
        for (int p = 0; p < PC_PAIRS; p++) {
            u64 x2 = *(const u64*)&xs2[p][k];
            acc[p][0] = ffma2(x2, wv.x, acc[p][0]);
            acc[p][1] = ffma2(x2, wv.y, acc[p][1]);
        }
    }

    float4 bv = *(const float4*)(b0 + u);
#pragma unroll
    for (int p = 0; p < PC_PAIRS; p++) {
        int pi = pbase + p;
        int b = pi / Tlen;
        int t = pi - b * Tlen;
        float2 lo, hi;
        asm("mov.b64 {%0, %1}, %2;" : "=f"(lo.x), "=f"(lo.y) : "l"(acc[p][0]));
        asm("mov.b64 {%0, %1}, %2;" : "=f"(hi.x), "=f"(hi.y) : "l"(acc[p][1]));
        float4 o = make_float4(lo.x + bv.x, lo.y + bv.y, hi.x + bv.z, hi.y + bv.w);
        *(float4*)(g_P0 + ((size_t)(t * Bsz) + b) * Udim + u) = o;
    }
}

// ---------------- kernel 2: persistent scan ----------------
// CTA (g, j): g = row group (16 rows), j = col slice (16 per group).
// Phase A: j<8 -> rk0 cols [64j..64j+64) -> h0 ; j>=8 -> rk1 cols -> r1.
// Phase B: k1 cols [32j..32j+32) -> h.
// Warp (q=w&3, hh=w>>2): K-slice 128, row half 8. Thread tile A: rows
// 8hh+rg+4i (i<2), cols cg+8jj (jj<8). B: jj<4. 4 reduction buffers (by q),
// stored in the H region (H is dead post-FMA; guarded by an extra sync).

__global__ void __launch_bounds__(NTHR, 1) rnn_kernel(
    const float* __restrict__ rk0, const float* __restrict__ rk1,
    const float* __restrict__ k1,  const float* __restrict__ b1,
    const float* __restrict__ wd,  const float* __restrict__ bd,
    float* __restrict__ out)
{
    extern __shared__ float sm[];
    const int tid  = threadIdx.x;
    const int g    = blockIdx.x >> 4;
    const int j    = blockIdx.x & 15;
    const int r0   = g * RPC;
    const int w    = tid >> 5;
    const int lane = tid & 31;
    const int q    = w & 3;          // K-slice [128q, 128q+128)
    const int hh   = w >> 2;         // rows [8hh, 8hh+8)
    const bool isA0 = (j < 8);

    unsigned* ctr = g_ctr + g * 32;

    // --- load weight slices into SMEM (once), transposed [col][K] ---
    const float* wsrcA = isA0 ? rk0 : rk1;
    const int cbaseA = (j & 7) * 64;
    for (int e = tid; e < 64 * Udim; e += NTHR) {
        int k = e >> 6, cc = e & 63;
        sm[OFF_WA + cc * PADK + k] = wsrcA[k * Udim + cbaseA + cc];
    }
    const int cbaseB = j * 32;
    for (int e = tid; e < 32 * Udim; e += NTHR) {
        int k = e >> 5, cc = e & 31;
        sm[OFF_WB + cc * PADK + k] = k1[k * Udim + cbaseB + cc];
    }

    // FMA lane geometry
    const int rg = lane & 3;
    const int cg = lane >> 2;

    // finalize geometry (256 threads): A 4 cols f4 / B 2 cols f2, row=tid>>4
    const int frow = tid >> 4;            // 0..15
    const int fcA  = (tid & 15) * 4;      // 0..60
    const int fcB  = (tid & 15) * 2;      // 0..30

    float4 b1v = make_float4(0.f, 0.f, 0.f, 0.f);
    if (!isA0) b1v = *(const float4*)(b1 + cbaseA + fcA);
    __syncthreads();

    const float* Hp  = sm + OFF_H  + 8 * hh * PADK + q * 128;
    const float* WpA = sm + OFF_WA + q * 128;
    const float* WpB = sm + OFF_WB + q * 128;
    float* redA = sm + OFF_RED + q * (16 * APAD);
    float* redB = sm + OFF_RED + q * (16 * BPAD);

    for (int t = 0; t < Tlen; t++) {
        // ================= Phase A: h @ [rk0 | rk1] =================
        float4 pv = make_float4(0.f, 0.f, 0.f, 0.f);
        if (isA0)  // static data, prefetch at top (hidden under load+FMA)
            pv = __ldcg((const float4*)(g_P0 + ((size_t)t * Bsz + r0 + frow) * Udim
                                        + cbaseA + fcA));

        load_ht(sm + OFF_H, g_h + r0 * Udim);
        __syncthreads();

        u64 acc[2][8];
#pragma unroll
        for (int i = 0; i < 2; i++)
#pragma unroll
            for (int jj = 0; jj < 8; jj++) acc[i][jj] = 0ull;

#pragma unroll 2
        for (int kc = 0; kc < 32; kc++) {
            const int k = kc * 4;
            ulonglong2 Wv[8];
#pragma unroll
            for (int jj = 0; jj < 8; jj++)
                Wv[jj] = *(const ulonglong2*)(WpA + (cg + 8 * jj) * PADK + k);
#pragma unroll
            for (int i = 0; i < 2; i++) {
                ulonglong2 Hv = *(const ulonglong2*)(Hp + (rg + 4 * i) * PADK + k);
#pragma unroll
                for (int jj = 0; jj < 8; jj++) {
                    acc[i][jj] = ffma2(Hv.x, Wv[jj].x, acc[i][jj]);
                    acc[i][jj] = ffma2(Hv.y, Wv[jj].y, acc[i][jj]);
                }
            }
        }
        __syncthreads();   // all warps done READING H before RED overwrites it

        // store partials into buffer q (bank = 8*rg + cg; conflict-free)
#pragma unroll
        for (int i = 0; i < 2; i++)
#pragma unroll
            for (int jj = 0; jj < 8; jj++)
                redA[(8 * hh + rg + 4 * i) * APAD + cg + 8 * jj] = fsum(acc[i][jj]);
        __syncthreads();

        // finalize: 4 outputs/thread (float4 over 4 K-slice partials)
        {
            float4 s = make_float4(0.f, 0.f, 0.f, 0.f);
#pragma unroll
            for (int p = 0; p < 4; p++) {
                float4 v = *(const float4*)(sm + OFF_RED + p * (16 * APAD)
                                            + frow * APAD + fcA);
                s.x += v.x; s.y += v.y; s.z += v.z; s.w += v.w;
            }
            int grow = (r0 + frow) * Udim + cbaseA + fcA;
            if (isA0) {
                float4 o;
                o.x = tanh_fast(s.x + pv.x);
                o.y = tanh_fast(s.y + pv.y);
                o.z = tanh_fast(s.z + pv.z);
                o.w = tanh_fast(s.w + pv.w);
                *(float4*)(g_h0 + grow) = o;
            } else {
                float4 o = make_float4(s.x + b1v.x, s.y + b1v.y,
                                       s.z + b1v.z, s.w + b1v.w);
                *(float4*)(g_r1 + grow) = o;
            }
        }
        gbar(ctr, (unsigned)(GSZ * (2 * t + 1)));   // arrive A + wait group A

        // ================= Phase B: h0 @ k1 =================
        float2 r1v = __ldcg((const float2*)(g_r1 + (size_t)(r0 + frow) * Udim
                                            + cbaseB + fcB));

        load_ht(sm + OFF_H, g_h0 + r0 * Udim);
        __syncthreads();

        u64 acc2[2][4];
#pragma unroll
        for (int i = 0; i < 2; i++)
#pragma unroll
            for (int jj = 0; jj < 4; jj++) acc2[i][jj] = 0ull;

#pragma unroll 2
        for (int kc = 0; kc < 32; kc++) {
            const int k = kc * 4;
            ulonglong2 Wv[4];
#pragma unroll
            for (int jj = 0; jj < 4; jj++)
                Wv[jj] = *(const ulonglong2*)(WpB + (cg + 8 * jj) * PADK + k);
#pragma unroll
            for (int i = 0; i < 2; i++) {
                ulonglong2 Hv = *(const ulonglong2*)(Hp + (rg + 4 * i) * PADK + k);
#pragma unroll
                for (int jj = 0; jj < 4; jj++) {
                    acc2[i][jj] = ffma2(Hv.x, Wv[jj].x, acc2[i][jj]);
                    acc2[i][jj] = ffma2(Hv.y, Wv[jj].y, acc2[i][jj]);
                }
            }
        }
        __syncthreads();   // H reads done before RED overwrite

        // store partials (bank = 8*rg + cg; conflict-free; BPAD=40)
#pragma unroll
        for (int i = 0; i < 2; i++)
#pragma unroll
            for (int jj = 0; jj < 4; jj++)
                redB[(8 * hh + rg + 4 * i) * BPAD + cg + 8 * jj] = fsum(acc2[i][jj]);
        __syncthreads();

        // finalize: 2 outputs/thread
        {
            float2 s = make_float2(0.f, 0.f);
#pragma unroll
            for (int p = 0; p < 4; p++) {
                float2 v = *(const float2*)(sm + OFF_RED + p * (16 * BPAD)
                                            + frow * BPAD + fcB);
                s.x += v.x; s.y += v.y;
            }
            int grow = (r0 + frow) * Udim + cbaseB + fcB;
            float2 o;
            o.x = tanh_fast(s.x + r1v.x);
            o.y = tanh_fast(s.y + r1v.y);
            *(float2*)(g_h + grow) = o;
        }
        gbar(ctr, (unsigned)(GSZ * (2 * t + 2)));   // arrive B + wait group B
    }

    // ---- output head: sigmoid(h @ wd + bd), CTA j==0 of each group ----
    if (j == 0) {
        int row = r0 + (tid >> 4);          // 16 rows, 16 threads each
        int p   = tid & 15;
        const float4* hv = (const float4*)(g_h + row * Udim + p * 32);
        const float4* wv = (const float4*)(wd + p * 32);
        float s = 0.f;
#pragma unroll
        for (int qq = 0; qq < 8; qq++) {
            float4 a = __ldcg(hv + qq);
            float4 b = wv[qq];
            s += a.x * b.x + a.y * b.y + a.z * b.z + a.w * b.w;
        }
        s += __shfl_xor_sync(0xffffffffu, s, 1);
        s += __shfl_xor_sync(0xffffffffu, s, 2);
        s += __shfl_xor_sync(0xffffffffu, s, 4);
        s += __shfl_xor_sync(0xffffffffu, s, 8);
        if (p == 0) out[row] = 1.0f / (1.0f + __expf(-(s + bd[0])));
    }
}

// ---------------- launch ----------------

extern "C" void kernel_launch(void* const* d_in, const int* in_sizes, int n_in,
                              void* d_out, int out_size) {
    const int*   tokens = (const int*)  d_in[0];
    const float* emb    = (const float*)d_in[1];
    const float* k0     = (const float*)d_in[2];
    const float* rk0    = (const float*)d_in[3];
    const float* b0     = (const float*)d_in[4];
    const float* k1     = (const float*)d_in[5];
    const float* rk1    = (const float*)d_in[6];
    const float* b1     = (const float*)d_in[7];
    const float* wd     = (const float*)d_in[8];
    const float* bd     = (const float*)d_in[9];
    float* out = (float*)d_out;

    (void)in_sizes; (void)n_in; (void)out_size;

    cudaFuncSetAttribute(rnn_kernel, cudaFuncAttributeMaxDynamicSharedMemorySize, SMEM_BYTES);

    pre_kernel<<<(Bsz * Tlen) / PC_PAIRS, PTHR>>>(tokens, emb, k0, b0);
    rnn_kernel<<<NCTA, NTHR, SMEM_BYTES>>>(rk0, rk1, k1, b1, wd, bd, out);
}

// round 14
// speedup vs baseline: 1.4143x; 1.0005x over previous
#include <cuda_runtime.h>
#include <cuda_bf16.h>

// Problem constants
#define Bsz   128
#define Tlen  80
#define Edim  100
#define Udim  512

// Launch shape: 8 row-groups (16 rows) x 16 col-slice CTAs, 8 warps/CTA.
// Warp (q, hh): q = K-slice [128q, 128q+128), hh = row half [8hh, 8hh+8).
#define NCTA  128
#define NTHR  256
#define GSZ   16
#define NGRP  8
#define RPC   16
#define PADK  516

#define APAD  72            // A reduction pad (bank 8*rg+cg; f4 reads 4-wf)
#define BPAD  40            // B reduction pad

// SMEM layout (float offsets). RED overlaps H (H dead after FMA; extra sync).
#define OFF_WA 0                          // 64 cols x PADK = 132096 B
#define OFF_WB (64 * PADK)                // 32 cols x PADK =  66048 B
#define OFF_H  (96 * PADK)                // 16 rows x PADK =  33024 B
#define OFF_RED OFF_H                     // 4 bufs x 16 x APAD = 18432 B (fits)
#define SMEM_FLOATS (OFF_H + RPC * PADK)
#define SMEM_BYTES  (SMEM_FLOATS * 4)     // 231168 B <= 232448

typedef unsigned long long u64;

// Device-global scratch
__device__ float g_P0[Tlen * Bsz * Udim];
__device__ float g_h [Bsz * Udim];
__device__ float g_h0[Bsz * Udim];
__device__ float g_r1[Bsz * Udim];
__device__ unsigned g_ctr[NGRP * 32];      // one counter per group, 128B apart

// ---------------- helpers ----------------

__device__ __forceinline__ u64 ffma2(u64 a, u64 b, u64 c) {
    u64 d;
    asm("fma.rn.f32x2 %0, %1, %2, %3;" : "=l"(d) : "l"(a), "l"(b), "l"(c));
    return d;
}

__device__ __forceinline__ float fsum(u64 v) {
    float lo, hi;
    asm("mov.b64 {%0, %1}, %2;" : "=f"(lo), "=f"(hi) : "l"(v));
    return lo + hi;
}

__device__ __forceinline__ float tanh_fast(float x) {
    float e = __expf(2.0f * x);
    return 1.0f - __fdividef(2.0f, e + 1.0f);
}

// Group barrier (R4-proven): monotonic counter, release-red arrive +
// acquire-load poll by ONE thread per CTA.
__device__ __forceinline__ void gbar(unsigned* ctr, unsigned target) {
    __syncthreads();
    if (threadIdx.x == 0) {
        asm volatile("red.release.gpu.global.add.u32 [%0], %1;"
                     :: "l"(ctr), "r"(1u) : "memory");
        unsigned v;
        do {
            asm volatile("ld.acquire.gpu.global.u32 %0, [%1];"
                         : "=r"(v) : "l"(ctr) : "memory");
        } while (v < target);
    }
    __syncthreads();
}

// Load 16 rows x 512 cols into padded SMEM tile (L2-only loads). 256 threads.
__device__ __forceinline__ void load_ht(float* HT, const float* src) {
    const float4* s = (const float4*)src;
#pragma unroll
    for (int i = 0; i < 8; i++) {
        int e = threadIdx.x + i * NTHR;      // 0..2047
        int r = e >> 7, kq = e & 127;
        float4 v = __ldcg(s + e);
        *(float4*)(HT + r * PADK + (kq << 2)) = v;
    }
}

// ---------------- kernel 1: P0 = emb[tokens] @ k0 + b0 ----------------

#define PC_PAIRS 16
#define PTHR 128

__global__ void __launch_bounds__(PTHR) pre_kernel(
    const int* __restrict__ tokens, const float* __restrict__ emb,
    const float* __restrict__ k0, const float* __restrict__ b0)
{
    __shared__ int    tok[PC_PAIRS];
    __shared__ float2 xs2[PC_PAIRS][Edim];

    const int tid = threadIdx.x;

    if (blockIdx.x == 0 && tid < NGRP) g_ctr[tid * 32] = 0u;

    if (blockIdx.x < 64) {
        int base = blockIdx.x * 1024 + tid * 8;
        float4 z = make_float4(0.f, 0.f, 0.f, 0.f);
        *(float4*)(g_h + base)     = z;
        *(float4*)(g_h + base + 4) = z;
    }

    const int pbase = blockIdx.x * PC_PAIRS;
    if (tid < PC_PAIRS) tok[tid] = tokens[pbase + tid];
    __syncthreads();

    for (int e = tid; e < PC_PAIRS * Edim; e += PTHR) {
        int p = e / Edim, k = e - p * Edim;
        float v = emb[tok[p] * Edim + k];
        xs2[p][k] = make_float2(v, v);
    }
    __syncthreads();

    const int u = tid * 4;
    u64 acc[PC_PAIRS][2];
#pragma unroll
    for (int p = 0; p < PC_PAIRS; p++) { acc[p][0] = 0ull; acc[p][1] = 0ull; }

    for (int k = 0; k < Edim; k++) {
        ulonglong2 wv = *(const ulonglong2*)(k0 + k * Udim + u);
#pragma unroll
        for (int p = 0; p < PC_PAIRS; p++) {
            u64 x2 = *(const u64*)&xs2[p][k];
            acc[p][0] = ffma2(x2, wv.x, acc[p][0]);
            acc[p][1] = ffma2(x2, wv.y, acc[p][1]);
        }
    }

    float4 bv = *(const float4*)(b0 + u);
#pragma unroll
    for (int p = 0; p < PC_PAIRS; p++) {
        int pi = pbase + p;
        int b = pi / Tlen;
        int t = pi - b * Tlen;
        float2 lo, hi;
        asm("mov.b64 {%0, %1}, %2;" : "=f"(lo.x), "=f"(lo.y) : "l"(acc[p][0]));
        asm("mov.b64 {%0, %1}, %2;" : "=f"(hi.x), "=f"(hi.y) : "l"(acc[p][1]));
        float4 o = make_float4(lo.x + bv.x, lo.y + bv.y, hi.x + bv.z, hi.y + bv.w);
        *(float4*)(g_P0 + ((size_t)(t * Bsz) + b) * Udim + u) = o;
    }
}

// ---------------- kernel 2: persistent scan ----------------
// CTA (g, j): g = row group (16 rows), j = col slice (16 per group).
// Phase A: j<8 -> rk0 cols [64j..64j+64) -> h0 ; j>=8 -> rk1 cols -> r1.
// Phase B: k1 cols [32j..32j+32) -> h.
// Warp (q=w&3, hh=w>>2): K-slice 128, row half 8. Thread tile A: rows
// 8hh+rg+4i (i<2), cols cg+8jj (jj<8). B: jj<4. 4 reduction buffers (by q),
// stored in the H region (H is dead post-FMA; guarded by an extra sync).

__global__ void __launch_bounds__(NTHR, 1) rnn_kernel(
    const float* __restrict__ rk0, const float* __restrict__ rk1,
    const float* __restrict__ k1,  const float* __restrict__ b1,
    const float* __restrict__ wd,  const float* __restrict__ bd,
    float* __restrict__ out)
{
    extern __shared__ float sm[];
    const int tid  = threadIdx.x;
    const int g    = blockIdx.x >> 4;
    const int j    = blockIdx.x & 15;
    const int r0   = g * RPC;
    const int w    = tid >> 5;
    const int lane = tid & 31;
    const int q    = w & 3;          // K-slice [128q, 128q+128)
    const int hh   = w >> 2;         // rows [8hh, 8hh+8)
    const bool isA0 = (j < 8);

    unsigned* ctr = g_ctr + g * 32;

    // --- load weight slices into SMEM (once), transposed [col][K] ---
    const float* wsrcA = isA0 ? rk0 : rk1;
    const int cbaseA = (j & 7) * 64;
    for (int e = tid; e < 64 * Udim; e += NTHR) {
        int k = e >> 6, cc = e & 63;
        sm[OFF_WA + cc * PADK + k] = wsrcA[k * Udim + cbaseA + cc];
    }
    const int cbaseB = j * 32;
    for (int e = tid; e < 32 * Udim; e += NTHR) {
        int k = e >> 5, cc = e & 31;
        sm[OFF_WB + cc * PADK + k] = k1[k * Udim + cbaseB + cc];
    }

    // FMA lane geometry
    const int rg = lane & 3;
    const int cg = lane >> 2;

    // finalize geometry (256 threads): A 4 cols f4 / B 2 cols f2, row=tid>>4
    const int frow = tid >> 4;            // 0..15
    const int fcA  = (tid & 15) * 4;      // 0..60
    const int fcB  = (tid & 15) * 2;      // 0..30

    float4 b1v = make_float4(0.f, 0.f, 0.f, 0.f);
    if (!isA0) b1v = *(const float4*)(b1 + cbaseA + fcA);
    __syncthreads();

    const float* Hp  = sm + OFF_H  + 8 * hh * PADK + q * 128;
    const float* WpA = sm + OFF_WA + q * 128;
    const float* WpB = sm + OFF_WB + q * 128;
    float* redA = sm + OFF_RED + q * (16 * APAD);
    float* redB = sm + OFF_RED + q * (16 * BPAD);

    for (int t = 0; t < Tlen; t++) {
        // ================= Phase A: h @ [rk0 | rk1] =================
        float4 pv = make_float4(0.f, 0.f, 0.f, 0.f);
        if (isA0)  // static data, prefetch at top (hidden under load+FMA)
            pv = __ldcg((const float4*)(g_P0 + ((size_t)t * Bsz + r0 + frow) * Udim
                                        + cbaseA + fcA));

        load_ht(sm + OFF_H, g_h + r0 * Udim);
        __syncthreads();

        u64 acc[2][8];
#pragma unroll
        for (int i = 0; i < 2; i++)
#pragma unroll
            for (int jj = 0; jj < 8; jj++) acc[i][jj] = 0ull;

#pragma unroll 2
        for (int kc = 0; kc < 32; kc++) {
            const int k = kc * 4;
            ulonglong2 Wv[8];
#pragma unroll
            for (int jj = 0; jj < 8; jj++)
                Wv[jj] = *(const ulonglong2*)(WpA + (cg + 8 * jj) * PADK + k);
#pragma unroll
            for (int i = 0; i < 2; i++) {
                ulonglong2 Hv = *(const ulonglong2*)(Hp + (rg + 4 * i) * PADK + k);
#pragma unroll
                for (int jj = 0; jj < 8; jj++) {
                    acc[i][jj] = ffma2(Hv.x, Wv[jj].x, acc[i][jj]);
                    acc[i][jj] = ffma2(Hv.y, Wv[jj].y, acc[i][jj]);
                }
            }
        }
        __syncthreads();   // all warps done READING H before RED overwrites it

        // store partials into buffer q (bank = 8*rg + cg; conflict-free)
#pragma unroll
        for (int i = 0; i < 2; i++)
#pragma unroll
            for (int jj = 0; jj < 8; jj++)
                redA[(8 * hh + rg + 4 * i) * APAD + cg + 8 * jj] = fsum(acc[i][jj]);
        __syncthreads();

        // finalize: 4 outputs/thread (float4 over 4 K-slice partials)
        {
            float4 s = make_float4(0.f, 0.f, 0.f, 0.f);
#pragma unroll
            for (int p = 0; p < 4; p++) {
                float4 v = *(const float4*)(sm + OFF_RED + p * (16 * APAD)
                                            + frow * APAD + fcA);
                s.x += v.x; s.y += v.y; s.z += v.z; s.w += v.w;
            }
            int grow = (r0 + frow) * Udim + cbaseA + fcA;
            if (isA0) {
                float4 o;
                o.x = tanh_fast(s.x + pv.x);
                o.y = tanh_fast(s.y + pv.y);
                o.z = tanh_fast(s.z + pv.z);
                o.w = tanh_fast(s.w + pv.w);
                *(float4*)(g_h0 + grow) = o;
            } else {
                float4 o = make_float4(s.x + b1v.x, s.y + b1v.y,
                                       s.z + b1v.z, s.w + b1v.w);
                *(float4*)(g_r1 + grow) = o;
            }
        }
        gbar(ctr, (unsigned)(GSZ * (2 * t + 1)));   // arrive A + wait group A

        // ================= Phase B: h0 @ k1 =================
        float2 r1v = __ldcg((const float2*)(g_r1 + (size_t)(r0 + frow) * Udim
                                            + cbaseB + fcB));

        load_ht(sm + OFF_H, g_h0 + r0 * Udim);
        __syncthreads();

        u64 acc2[2][4];
#pragma unroll
        for (int i = 0; i < 2; i++)
#pragma unroll
            for (int jj = 0; jj < 4; jj++) acc2[i][jj] = 0ull;

#pragma unroll 2
        for (int kc = 0; kc < 32; kc++) {
            const int k = kc * 4;
            ulonglong2 Wv[4];
#pragma unroll
            for (int jj = 0; jj < 4; jj++)
                Wv[jj] = *(const ulonglong2*)(WpB + (cg + 8 * jj) * PADK + k);
#pragma unroll
            for (int i = 0; i < 2; i++) {
                ulonglong2 Hv = *(const ulonglong2*)(Hp + (rg + 4 * i) * PADK + k);
#pragma unroll
                for (int jj = 0; jj < 4; jj++) {
                    acc2[i][jj] = ffma2(Hv.x, Wv[jj].x, acc2[i][jj]);
                    acc2[i][jj] = ffma2(Hv.y, Wv[jj].y, acc2[i][jj]);
                }
            }
        }
        __syncthreads();   // H reads done before RED overwrite

        // store partials (bank = 8*rg + cg; conflict-free; BPAD=40)
#pragma unroll
        for (int i = 0; i < 2; i++)
#pragma unroll
            for (int jj = 0; jj < 4; jj++)
                redB[(8 * hh + rg + 4 * i) * BPAD + cg + 8 * jj] = fsum(acc2[i][jj]);
        __syncthreads();

        // finalize: 2 outputs/thread
        {
            float2 s = make_float2(0.f, 0.f);
#pragma unroll
            for (int p = 0; p < 4; p++) {
                float2 v = *(const float2*)(sm + OFF_RED + p * (16 * BPAD)
                                            + frow * BPAD + fcB);
                s.x += v.x; s.y += v.y;
            }
            int grow = (r0 + frow) * Udim + cbaseB + fcB;
            float2 o;
            o.x = tanh_fast(s.x + r1v.x);
            o.y = tanh_fast(s.y + r1v.y);
            *(float2*)(g_h + grow) = o;
        }
        gbar(ctr, (unsigned)(GSZ * (2 * t + 2)));   // arrive B + wait group B
    }

    // ---- output head: sigmoid(h @ wd + bd), CTA j==0 of each group ----
    if (j == 0) {
        int row = r0 + (tid >> 4);          // 16 rows, 16 threads each
        int p   = tid & 15;
        const float4* hv = (const float4*)(g_h + row * Udim + p * 32);
        const float4* wv = (const float4*)(wd + p * 32);
        float s = 0.f;
#pragma unroll
        for (int qq = 0; qq < 8; qq++) {
            float4 a = __ldcg(hv + qq);
            float4 b = wv[qq];
            s += a.x * b.x + a.y * b.y + a.z * b.z + a.w * b.w;
        }
        s += __shfl_xor_sync(0xffffffffu, s, 1);
        s += __shfl_xor_sync(0xffffffffu, s, 2);
        s += __shfl_xor_sync(0xffffffffu, s, 4);
        s += __shfl_xor_sync(0xffffffffu, s, 8);
        if (p == 0) out[row] = 1.0f / (1.0f + __expf(-(s + bd[0])));
    }
}

// ---------------- launch ----------------

extern "C" void kernel_launch(void* const* d_in, const int* in_sizes, int n_in,
                              void* d_out, int out_size) {
    const int*   tokens = (const int*)  d_in[0];
    const float* emb    = (const float*)d_in[1];
    const float* k0     = (const float*)d_in[2];
    const float* rk0    = (const float*)d_in[3];
    const float* b0     = (const float*)d_in[4];
    const float* k1     = (const float*)d_in[5];
    const float* rk1    = (const float*)d_in[6];
    const float* b1     = (const float*)d_in[7];
    const float* wd     = (const float*)d_in[8];
    const float* bd     = (const float*)d_in[9];
    float* out = (float*)d_out;

    (void)in_sizes; (void)n_in; (void)out_size;

    cudaFuncSetAttribute(rnn_kernel, cudaFuncAttributeMaxDynamicSharedMemorySize, SMEM_BYTES);

    pre_kernel<<<(Bsz * Tlen) / PC_PAIRS, PTHR>>>(tokens, emb, k0, b0);
    rnn_kernel<<<NCTA, NTHR, SMEM_BYTES>>>(rk0, rk1, k1, b1, wd, bd, out);
}

// round 15
// speedup vs baseline: 1.4232x; 1.0063x over previous
#include <cuda_runtime.h>
#include <cuda_bf16.h>

#define Bsz   128
#define Tlen  80
#define Edim  100
#define Udim  512

// 8 row-groups (16 rows) x 16 col-slice CTAs, 8 warps/CTA.
// Warp (q=w&3, hh=w>>2): K-slice [128q,128q+128), rows [8hh,8hh+8).
#define NCTA  128
#define NTHR  256
#define GSZ   16
#define NGRP  8
#define RPC   16
#define PADK  516
#define APAD  72
#define BPAD  40

#define OFF_WA 0                          // 64 cols x PADK
#define OFF_WB (64 * PADK)                // 32 cols x PADK
#define OFF_H  (96 * PADK)                // 16 rows x PADK (strip area)
#define OFF_RED OFF_H                     // RED overlaps H (H dead post-FMA)
#define OFF_FLAG (OFF_H + RPC * PADK)     // 1 word + pad
#define SMEM_FLOATS (OFF_FLAG + 32)
#define SMEM_BYTES  (SMEM_FLOATS * 4)     // 231296 B <= 232448

typedef unsigned long long u64;

__device__ float g_P0[Tlen * Bsz * Udim];
__device__ float g_h [Bsz * Udim];
__device__ float g_h0[Bsz * Udim];
__device__ float g_r1[Bsz * Udim];
__device__ unsigned g_ctr[NGRP * 32];

// ---------------- helpers ----------------

__device__ __forceinline__ u64 ffma2(u64 a, u64 b, u64 c) {
    u64 d;
    asm("fma.rn.f32x2 %0, %1, %2, %3;" : "=l"(d) : "l"(a), "l"(b), "l"(c));
    return d;
}
__device__ __forceinline__ float fsum(u64 v) {
    float lo, hi;
    asm("mov.b64 {%0, %1}, %2;" : "=f"(lo), "=f"(hi) : "l"(v));
    return lo + hi;
}
__device__ __forceinline__ float tanh_fast(float x) {
    float e = __expf(2.0f * x);
    return 1.0f - __fdividef(2.0f, e + 1.0f);
}
__device__ __forceinline__ void st_rel_cta(unsigned* p, unsigned v) {
    asm volatile("st.release.cta.u32 [%0], %1;" :: "l"(p), "r"(v) : "memory");
}
__device__ __forceinline__ unsigned ld_acq_cta(const unsigned* p) {
    unsigned v;
    asm volatile("ld.acquire.cta.u32 %0, [%1];" : "=r"(v) : "l"(p) : "memory");
    return v;
}

// Barrier with warp-independent release. Leading __syncthreads orders all
// local stores (and finalize reads of RED) before arrive / strip overwrite.
// tid0 is the single global poller (L2-safe); publishes via SMEM flag.
__device__ __forceinline__ void gwait(unsigned* ctr, unsigned target,
                                      unsigned* flag, unsigned phase) {
    __syncthreads();
    if (threadIdx.x == 0) {
        asm volatile("red.release.gpu.global.add.u32 [%0], %1;"
                     :: "l"(ctr), "r"(1u) : "memory");
        unsigned v;
        do {
            asm volatile("ld.acquire.gpu.global.u32 %0, [%1];"
                         : "=r"(v) : "l"(ctr) : "memory");
        } while (v < target);
        st_rel_cta(flag, phase);
    }
    while (ld_acq_cta(flag) < phase) { }
}

// Warp loads its own 8-row x 128-col window: src row stride Udim,
// dest row stride PADK. 8x coalesced LDG.128 (512B/row), 8x STS.128
// (consecutive f4 -> conflict-free). __syncwarp only.
__device__ __forceinline__ void load_strip(float* HTw, const float* src) {
    const int lane = threadIdx.x & 31;
    float4 v[8];
#pragma unroll
    for (int r = 0; r < 8; r++)
        v[r] = __ldcg((const float4*)(src + r * Udim) + lane);
#pragma unroll
    for (int r = 0; r < 8; r++)
        *(float4*)(HTw + r * PADK + lane * 4) = v[r];
    __syncwarp();
}

// ---------------- kernel 1: P0 = emb[tokens] @ k0 + b0 ----------------

#define PC_PAIRS 16
#define PTHR 128

__global__ void __launch_bounds__(PTHR) pre_kernel(
    const int* __restrict__ tokens, const float* __restrict__ emb,
    const float* __restrict__ k0, const float* __restrict__ b0)
{
    __shared__ int    tok[PC_PAIRS];
    __shared__ float2 xs2[PC_PAIRS][Edim];

    const int tid = threadIdx.x;

    if (blockIdx.x == 0 && tid < NGRP) g_ctr[tid * 32] = 0u;

    if (blockIdx.x < 64) {
        int base = blockIdx.x * 1024 + tid * 8;
        float4 z = make_float4(0.f, 0.f, 0.f, 0.f);
        *(float4*)(g_h + base)     = z;
        *(float4*)(g_h + base + 4) = z;
    }

    const int pbase = blockIdx.x * PC_PAIRS;
    if (tid < PC_PAIRS) tok[tid] = tokens[pbase + tid];
    __syncthreads();

    for (int e = tid; e < PC_PAIRS * Edim; e += PTHR) {
        int p = e / Edim, k = e - p * Edim;
        float v = emb[tok[p] * Edim + k];
        xs2[p][k] = make_float2(v, v);
    }
    __syncthreads();

    const int u = tid * 4;
    u64 acc[PC_PAIRS][2];
#pragma unroll
    for (int p = 0; p < PC_PAIRS; p++) { acc[p][0] = 0ull; acc[p][1] = 0ull; }

    for (int k = 0; k < Edim; k++) {
        ulonglong2 wv = *(const ulonglong2*)(k0 + k * Udim + u);
#pragma unroll
        for (int p = 0; p < PC_PAIRS; p++) {
            u64 x2 = *(const u64*)&xs2[p][k];
            acc[p][0] = ffma2(x2, wv.x, acc[p][0]);
            acc[p][1] = ffma2(x2, wv.y, acc[p][1]);
        }
    }

    float4 bv = *(const float4*)(b0 + u);
#pragma unroll
    for (int p = 0; p < PC_PAIRS; p++) {
        int pi = pbase + p;
        int b = pi / Tlen;
        int t = pi - b * Tlen;
        float2 lo, hi;
        asm("mov.b64 {%0, %1}, %2;" : "=f"(lo.x), "=f"(lo.y) : "l"(acc[p][0]));
        asm("mov.b64 {%0, %1}, %2;" : "=f"(hi.x), "=f"(hi.y) : "l"(acc[p][1]));
        float4 o = make_float4(lo.x + bv.x, lo.y + bv.y, hi.x + bv.z, hi.y + bv.w);
        *(float4*)(g_P0 + ((size_t)(t * Bsz) + b) * Udim + u) = o;
    }
}

// ---------------- kernel 2: persistent scan ----------------

__global__ void __launch_bounds__(NTHR, 1) rnn_kernel(
    const float* __restrict__ rk0, const float* __restrict__ rk1,
    const float* __restrict__ k1,  const float* __restrict__ b1,
    const float* __restrict__ wd,  const float* __restrict__ bd,
    float* __restrict__ out)
{
    extern __shared__ float sm[];
    const int tid  = threadIdx.x;
    const int g    = blockIdx.x >> 4;
    const int j    = blockIdx.x & 15;
    const int r0   = g * RPC;
    const int w    = tid >> 5;
    const int lane = tid & 31;
    const int q    = w & 3;
    const int hh   = w >> 2;
    const bool isA0 = (j < 8);

    unsigned* ctr  = g_ctr + g * 32;
    unsigned* flag = (unsigned*)(sm + OFF_FLAG);

    // weights into SMEM (once), transposed [col][K]
    const float* wsrcA = isA0 ? rk0 : rk1;
    const int cbaseA = (j & 7) * 64;
    for (int e = tid; e < 64 * Udim; e += NTHR) {
        int k = e >> 6, cc = e & 63;
        sm[OFF_WA + cc * PADK + k] = wsrcA[k * Udim + cbaseA + cc];
    }
    const int cbaseB = j * 32;
    for (int e = tid; e < 32 * Udim; e += NTHR) {
        int k = e >> 5, cc = e & 31;
        sm[OFF_WB + cc * PADK + k] = k1[k * Udim + cbaseB + cc];
    }

    const int rg = lane & 3;
    const int cg = lane >> 2;

    const int frow = tid >> 4;            // 0..15
    const int fcA  = (tid & 15) * 4;
    const int fcB  = (tid & 15) * 2;

    float4 b1v = make_float4(0.f, 0.f, 0.f, 0.f);
    if (!isA0) b1v = *(const float4*)(b1 + cbaseA + fcA);
    if (tid == 0) *flag = 0u;
    __syncthreads();

    const float* Hp  = sm + OFF_H + 8 * hh * PADK + q * 128;
    float*       HTw = sm + OFF_H + 8 * hh * PADK + q * 128;
    const float* WpA = sm + OFF_WA + q * 128;
    const float* WpB = sm + OFF_WB + q * 128;
    float* redA = sm + OFF_RED + q * (16 * APAD);
    float* redB = sm + OFF_RED + q * (16 * BPAD);

    for (int t = 0; t < Tlen; t++) {
        // ============ Phase A: h @ [rk0 | rk1] ============
        float4 pv = make_float4(0.f, 0.f, 0.f, 0.f);
        if (isA0)
            pv = __ldcg((const float4*)(g_P0 + ((size_t)t * Bsz + r0 + frow) * Udim
                                        + cbaseA + fcA));

        load_strip(HTw, g_h + (size_t)(r0 + 8 * hh) * Udim + 128 * q);

        u64 acc[2][8];
#pragma unroll
        for (int i = 0; i < 2; i++)
#pragma unroll
            for (int jj = 0; jj < 8; jj++) acc[i][jj] = 0ull;

#pragma unroll 2
        for (int kc = 0; kc < 32; kc++) {
            const int k = kc * 4;
            ulonglong2 Wv[8];
#pragma unroll
            for (int jj = 0; jj < 8; jj++)
                Wv[jj] = *(const ulonglong2*)(WpA + (cg + 8 * jj) * PADK + k);
#pragma unroll
            for (int i = 0; i < 2; i++) {
                ulonglong2 Hv = *(const ulonglong2*)(Hp + (rg + 4 * i) * PADK + k);
#pragma unroll
                for (int jj = 0; jj < 8; jj++) {
                    acc[i][jj] = ffma2(Hv.x, Wv[jj].x, acc[i][jj]);
                    acc[i][jj] = ffma2(Hv.y, Wv[jj].y, acc[i][jj]);
                }
            }
        }
        __syncthreads();   // H reads done before RED overwrite

#pragma unroll
        for (int i = 0; i < 2; i++)
#pragma unroll
            for (int jj = 0; jj < 8; jj++)
                redA[(8 * hh + rg + 4 * i) * APAD + cg + 8 * jj] = fsum(acc[i][jj]);
        __syncthreads();

        {
            float4 s = make_float4(0.f, 0.f, 0.f, 0.f);
#pragma unroll
            for (int p = 0; p < 4; p++) {
                float4 v = *(const float4*)(sm + OFF_RED + p * (16 * APAD)
                                            + frow * APAD + fcA);
                s.x += v.x; s.y += v.y; s.z += v.z; s.w += v.w;
            }
            int grow = (r0 + frow) * Udim + cbaseA + fcA;
            if (isA0) {
                float4 o;
                o.x = tanh_fast(s.x + pv.x);
                o.y = tanh_fast(s.y + pv.y);
                o.z = tanh_fast(s.z + pv.z);
                o.w = tanh_fast(s.w + pv.w);
                *(float4*)(g_h0 + grow) = o;
            } else {
                *(float4*)(g_r1 + grow) = make_float4(s.x + b1v.x, s.y + b1v.y,
                                                      s.z + b1v.z, s.w + b1v.w);
            }
        }
        gwait(ctr, (unsigned)(GSZ * (2 * t + 1)), flag, (unsigned)(2 * t + 1));

        // ============ Phase B: h0 @ k1 ============
        float2 r1v = __ldcg((const float2*)(g_r1 + (size_t)(r0 + frow) * Udim
                                            + cbaseB + fcB));

        load_strip(HTw, g_h0 + (size_t)(r0 + 8 * hh) * Udim + 128 * q);

        u64 acc2[2][4];
#pragma unroll
        for (int i = 0; i < 2; i++)
#pragma unroll
            for (int jj = 0; jj < 4; jj++) acc2[i][jj] = 0ull;

#pragma unroll 2
        for (int kc = 0; kc < 32; kc++) {
            const int k = kc * 4;
            ulonglong2 Wv[4];
#pragma unroll
            for (int jj = 0; jj < 4; jj++)
                Wv[jj] = *(const ulonglong2*)(WpB + (cg + 8 * jj) * PADK + k);
#pragma unroll
            for (int i = 0; i < 2; i++) {
                ulonglong2 Hv = *(const ulonglong2*)(Hp + (rg + 4 * i) * PADK + k);
#pragma unroll
                for (int jj = 0; jj < 4; jj++) {
                    acc2[i][jj] = ffma2(Hv.x, Wv[jj].x, acc2[i][jj]);
                    acc2[i][jj] = ffma2(Hv.y, Wv[jj].y, acc2[i][jj]);
                }
            }
        }
        __syncthreads();

#pragma unroll
        for (int i = 0; i < 2; i++)
#pragma unroll
            for (int jj = 0; jj < 4; jj++)
                redB[(8 * hh + rg + 4 * i) * BPAD + cg + 8 * jj] = fsum(acc2[i][jj]);
        __syncthreads();

        {
            float2 s = make_float2(0.f, 0.f);
#pragma unroll
            for (int p = 0; p < 4; p++) {
                float2 v = *(const float2*)(sm + OFF_RED + p * (16 * BPAD)
                                            + frow * BPAD + fcB);
                s.x += v.x; s.y += v.y;
            }
            int grow = (r0 + frow) * Udim + cbaseB + fcB;
            float2 o;
            o.x = tanh_fast(s.x + r1v.x);
            o.y = tanh_fast(s.y + r1v.y);
            *(float2*)(g_h + grow) = o;
        }
        gwait(ctr, (unsigned)(GSZ * (2 * t + 2)), flag, (unsigned)(2 * t + 2));
    }

    // ---- output head: sigmoid(h @ wd + bd), CTA j==0 of each group ----
    if (j == 0) {
        int row = r0 + (tid >> 4);
        int p   = tid & 15;
        const float4* hv = (const float4*)(g_h + row * Udim + p * 32);
        const float4* wv = (const float4*)(wd + p * 32);
        float s = 0.f;
#pragma unroll
        for (int qq = 0; qq < 8; qq++) {
            float4 a = __ldcg(hv + qq);
            float4 b = wv[qq];
            s += a.x * b.x + a.y * b.y + a.z * b.z + a.w * b.w;
        }
        s += __shfl_xor_sync(0xffffffffu, s, 1);
        s += __shfl_xor_sync(0xffffffffu, s, 2);
        s += __shfl_xor_sync(0xffffffffu, s, 4);
        s += __shfl_xor_sync(0xffffffffu, s, 8);
        if (p == 0) out[row] = 1.0f / (1.0f + __expf(-(s + bd[0])));
    }
}

// ---------------- launch ----------------

extern "C" void kernel_launch(void* const* d_in, const int* in_sizes, int n_in,
                              void* d_out, int out_size) {
    const int*   tokens = (const int*)  d_in[0];
    const float* emb    = (const float*)d_in[1];
    const float* k0     = (const float*)d_in[2];
    const float* rk0    = (const float*)d_in[3];
    const float* b0     = (const float*)d_in[4];
    const float* k1     = (const float*)d_in[5];
    const float* rk1    = (const float*)d_in[6];
    const float* b1     = (const float*)d_in[7];
    const float* wd     = (const float*)d_in[8];
    const float* bd     = (const float*)d_in[9];
    float* out = (float*)d_out;

    (void)in_sizes; (void)n_in; (void)out_size;

    cudaFuncSetAttribute(rnn_kernel, cudaFuncAttributeMaxDynamicSharedMemorySize, SMEM_BYTES);

    pre_kernel<<<(Bsz * Tlen) / PC_PAIRS, PTHR>>>(tokens, emb, k0, b0);
    rnn_kernel<<<NCTA, NTHR, SMEM_BYTES>>>(rk0, rk1, k1, b1, wd, bd, out);
}